// round 11
// baseline (speedup 1.0000x reference)
#include <cuda_runtime.h>
#include <math.h>

// ---------------------------------------------------------------------------
// SinkhornDistance: N=4, P1=P2=1024, D=16, EPS=0.1, MAX_ITER=100, THRESH=0.1
// Outputs (concatenated fp32): cost[4], pi[4*1024*1024], C[4*1024*1024]
// Round 11: 1024 threads/block (8 warps/SMSP for latency hiding). Each warp
// owns 1 row (SMEM tile) + 1 column (CT read from L2 each iter — constant,
// coalesced, hideable). Sync structure identical to R10 (merged BAR+gbarA,
// warp-15 publication, lagged done check).
// ---------------------------------------------------------------------------

#define NB 4
#define P  1024
#define DD 16
#define EPSF 0.1f
#define KAP 14.426950408889634f        // log2(e)/eps
#define EPSLN2 0.06931471805599453f    // eps*ln2 = 1/KAP
#define MAX_ITER 100
#define THRESHF 0.1f
#define SBLOCKS 128
#define GBLK 32                        // blocks per batch group
#define STHREADS 1024
#define PLANE (NB*P*P)

// ----------------------------- scratch (static device memory) ---------------
struct __align__(32) Flag { int v; int pad[7]; };
struct __align__(128) BigFlag { int v; int pad[31]; };
__device__ Flag     g_gflags[NB][GBLK];  // per-group arrival flags (32B apart)
__device__ BigFlag  g_ggo[NB];           // per-group go words (128B apart)
__device__ int      g_epoch[NB];         // last iteration published per group
__device__ float    g_errSum[NB][2];     // per-group err, ring by iter parity
__device__ float    g_CT[PLANE];         // transposed cost matrix (16 MB)
__device__ float    g_u[NB*P];           // kappa-scaled u
__device__ float    g_v[NB*P];           // kappa-scaled v
__device__ float    g_logmu[NB*P];
__device__ float    g_lognu[NB*P];
__device__ float    g_errPart[SBLOCKS];
__device__ float    g_rowPart[NB*P];

// ----------------------------- helpers --------------------------------------
__device__ __forceinline__ float ex2(float x) {
    float r; asm("ex2.approx.ftz.f32 %0, %1;" : "=f"(r) : "f"(x)); return r;
}
__device__ __forceinline__ float lg2(float x) {
    float r; asm("lg2.approx.ftz.f32 %0, %1;" : "=f"(r) : "f"(x)); return r;
}
__device__ __forceinline__ int ld_acq(const int* p) {
    int v; asm volatile("ld.acquire.gpu.s32 %0, [%1];" : "=r"(v) : "l"(p)); return v;
}
__device__ __forceinline__ void st_rel(int* p, int v) {
    asm volatile("st.release.gpu.s32 [%0], %1;" :: "l"(p), "r"(v));
}

// R8-style leader 2-hop group barrier (proven).
__device__ __forceinline__ void gbar(int n, int bb, int epoch) {
    __syncthreads();
    if (bb == 0) {
        if (threadIdx.x < 32) {
            int lane = threadIdx.x;
            if (lane == 0) st_rel(&g_gflags[n][0].v, epoch);
            bool ok;
            do { ok = ld_acq(&g_gflags[n][lane].v) >= epoch; }
            while (!__all_sync(0xffffffffu, ok));
            if (lane == 0) st_rel(&g_ggo[n].v, epoch);
        }
    } else if (threadIdx.x == 0) {
        st_rel(&g_gflags[n][bb].v, epoch);
        while (ld_acq(&g_ggo[n].v) < epoch) { }
    }
    __syncthreads();
}

// ----------------------------- kernel 0: init -------------------------------
__global__ void k_init(const float* __restrict__ wx, const float* __restrict__ wy) {
    int i = blockIdx.x * blockDim.x + threadIdx.x;   // 4096 threads total
    g_v[i] = 0.f;
    g_u[i] = 0.f;
    g_logmu[i] = logf(wx[i] + 1e-8f);
    g_lognu[i] = logf(wy[i] + 1e-8f);
}

// ----------------------------- kernel 1: cost matrix C and CT ---------------
__global__ void k_cost(const float* __restrict__ x, const float* __restrict__ y,
                       float* __restrict__ C) {
    __shared__ float xs[32][17];
    __shared__ float ys[32][17];
    __shared__ float tile[32][33];
    int n = blockIdx.z, I = blockIdx.y, J = blockIdx.x;
    int tid = threadIdx.x;   // 256

    for (int e = tid; e < 32 * DD; e += 256)
        xs[e >> 4][e & 15] = x[((size_t)(n * P + I * 32 + (e >> 4))) * DD + (e & 15)];
    for (int e = tid; e < 32 * DD; e += 256)
        ys[e >> 4][e & 15] = y[((size_t)(n * P + J * 32 + (e >> 4))) * DD + (e & 15)];
    __syncthreads();

    int ii = tid >> 3;
    int j0 = (tid & 7) * 4;
#pragma unroll
    for (int q = 0; q < 4; ++q) {
        int jj = j0 + q;
        float s = 0.f;
#pragma unroll
        for (int d = 0; d < DD; ++d) s += fabsf(xs[ii][d] - ys[jj][d]);
        tile[ii][jj] = s;
    }
    __syncthreads();

    for (int e = tid; e < 1024; e += 256) {
        int r = e >> 5, c = e & 31;
        C[((size_t)(n * P + I * 32 + r)) * P + (J * 32 + c)]    = tile[r][c];
        g_CT[((size_t)(n * P + J * 32 + r)) * P + (I * 32 + c)] = tile[c][r];
    }
}

// ----------------------------- kernel 2: barrier state reset ----------------
__global__ void k_flags() {
    int i = threadIdx.x;   // 128
    ((Flag*)g_gflags)[i].v = 0;
    if (i < NB) {
        g_ggo[i].v = 0;
        g_epoch[i] = -1;
    }
}

// ----------------------------- kernel 3: persistent Sinkhorn ----------------
// SMEM: tile[32][1024] (kappa*C rows) | shv[1024] staging | sdu[32]
__global__ void __launch_bounds__(STHREADS, 1)
k_sink(const float* __restrict__ C, float* __restrict__ pi) {
    extern __shared__ __align__(16) float smem[];
    float* tile = smem;                  // 32*1024
    float* shv  = smem + 32 * 1024;      // 1024 (kv, then ku)
    float* sdu  = shv + 1024;            // 32
    __shared__ int sdone;

    int tid = threadIdx.x;
    int w = tid >> 5, lane = tid & 31;   // 32 warps
    int b = blockIdx.x;
    int n = b >> 5, bb = b & 31;
    int r = (b << 5) + w;                // this warp's global row
    int jc = (bb << 5) + w;              // this warp's column (within batch)

    // ---- prologue: row tile (kappa*C), coalesced ----
    {
        const float4* src = (const float4*)(C + ((size_t)b << 15));
        float4* dst = (float4*)tile;
#pragma unroll
        for (int k = 0; k < 8; ++k) {
            float4 c = __ldcg(&src[tid + (k << 10)]);
            c.x *= KAP; c.y *= KAP; c.z *= KAP; c.w *= KAP;
            dst[tid + (k << 10)] = c;
        }
    }
    const float4* ct4 = (const float4*)(g_CT + (((size_t)((n << 10) + jc)) << 10));
    float lmu = g_logmu[r];
    float lnu = g_lognu[(n << 10) + jc];
    float up = 0.f;                       // previous raw u of own row
    int ep = 1;
    __syncthreads();

    for (int it = 0; it < MAX_ITER; ++it) {
        // ---- stage kappa*v + lagged done check (warp0 lanes 0-3 parallel) ----
        shv[tid] = __ldcg(&g_v[(n << 10) + tid]);
        if (w == 0) {
            int d = 0;
            if (it > 0) {
                int need = it - 1;
                if (lane < 4) { while (ld_acq(&g_epoch[lane]) < need) { } }
                __syncwarp();
                float e = (lane < 4) ? __ldcg(&g_errSum[lane][need & 1]) : 0.f;
                e += __shfl_xor_sync(0xffffffffu, e, 1);
                e += __shfl_xor_sync(0xffffffffu, e, 2);
                e = __shfl_sync(0xffffffffu, e, 0);
                d = (e * 0.25f < THRESHF) ? 1 : 0;
            }
            if (lane == 0) sdone = d;
        }
        __syncthreads();                         // BAR1: shv + sdone
        if (sdone) break;

        // ---- u-phase: row w from SMEM tile ----
        {
            const float* trow = tile + (w << 10);
            float t[16];
            float m1 = -3.0e38f;
#pragma unroll
            for (int k = 0; k < 4; ++k) {
                int idx = (lane << 2) + (k << 7);
                float4 c = *(const float4*)(trow + idx);
                float4 v = *(const float4*)(shv + idx);
                float a0 = v.x - c.x, a1 = v.y - c.y;
                float a2 = v.z - c.z, a3 = v.w - c.w;
                t[(k << 2) + 0] = a0; t[(k << 2) + 1] = a1;
                t[(k << 2) + 2] = a2; t[(k << 2) + 3] = a3;
                m1 = fmaxf(m1, fmaxf(fmaxf(a0, a1), fmaxf(a2, a3)));
            }
#pragma unroll
            for (int o = 16; o; o >>= 1) m1 = fmaxf(m1, __shfl_xor_sync(0xffffffffu, m1, o));
            float s1 = 0.f;
#pragma unroll
            for (int q = 0; q < 16; ++q) s1 += ex2(t[q] - m1);

            float m2 = -3.0e38f;
#pragma unroll
            for (int k = 4; k < 8; ++k) {
                int idx = (lane << 2) + (k << 7);
                float4 c = *(const float4*)(trow + idx);
                float4 v = *(const float4*)(shv + idx);
                float a0 = v.x - c.x, a1 = v.y - c.y;
                float a2 = v.z - c.z, a3 = v.w - c.w;
                t[((k - 4) << 2) + 0] = a0; t[((k - 4) << 2) + 1] = a1;
                t[((k - 4) << 2) + 2] = a2; t[((k - 4) << 2) + 3] = a3;
                m2 = fmaxf(m2, fmaxf(fmaxf(a0, a1), fmaxf(a2, a3)));
            }
#pragma unroll
            for (int o = 16; o; o >>= 1) m2 = fmaxf(m2, __shfl_xor_sync(0xffffffffu, m2, o));
            float s2 = 0.f;
#pragma unroll
            for (int q = 0; q < 16; ++q) s2 += ex2(t[q] - m2);

            float M = fmaxf(m1, m2);
            float S = s1 * ex2(m1 - M) + s2 * ex2(m2 - M);
#pragma unroll
            for (int o = 16; o; o >>= 1) S += __shfl_xor_sync(0xffffffffu, S, o);
            float u_raw = EPSF * lmu - EPSLN2 * (M + lg2(S));

            if (lane == 0) {
                sdu[w] = fabsf(u_raw - up);
                __stcg(&g_u[r], u_raw * KAP);
            }
            up = u_raw;
        }

        // ---- merged BAR2 + gbarA: err reduce inside the barrier's warp0 ----
        __syncthreads();                         // covers sdu + g_u stores
        if (w == 0) {
            float e = sdu[lane];
#pragma unroll
            for (int o = 16; o; o >>= 1) e += __shfl_xor_sync(0xffffffffu, e, o);
            if (lane == 0) {
                __stcg(&g_errPart[b], e);
                st_rel(&g_gflags[n][bb].v, ep);  // release orders errPart + g_u
            }
            if (bb == 0) {
                bool ok;
                do { ok = ld_acq(&g_gflags[n][lane].v) >= ep; }
                while (!__all_sync(0xffffffffu, ok));
                if (lane == 0) st_rel(&g_ggo[n].v, ep);
            } else if (lane == 0) {
                while (ld_acq(&g_ggo[n].v) < ep) { }
            }
        }
        __syncthreads();
        ep++;

        // ---- err(it) + epoch published by warp 15 of group leader block ----
        if (bb == 0 && w == 15) {
            float e = __ldcg(&g_errPart[(n << 5) + lane]);
#pragma unroll
            for (int o = 16; o; o >>= 1) e += __shfl_xor_sync(0xffffffffu, e, o);
            if (lane == 0) {
                __stcg(&g_errSum[n][it & 1], e);
                st_rel(&g_epoch[n], it);
            }
        }

        // ---- stage kappa*u ----
        shv[tid] = __ldcg(&g_u[(n << 10) + tid]);
        __syncthreads();                         // BAR3: shv = kappa*u

        // ---- v-phase: column jc, CT read from L2 (constant, coalesced) ----
        {
            float t[16];
            float m1 = -3.0e38f;
#pragma unroll
            for (int k = 0; k < 4; ++k) {
                int i4 = (k << 5) + lane;
                float4 c = __ldcg(&ct4[i4]);
                float4 v = *(const float4*)(shv + (i4 << 2));
                float a0 = fmaf(c.x, -KAP, v.x), a1 = fmaf(c.y, -KAP, v.y);
                float a2 = fmaf(c.z, -KAP, v.z), a3 = fmaf(c.w, -KAP, v.w);
                t[(k << 2) + 0] = a0; t[(k << 2) + 1] = a1;
                t[(k << 2) + 2] = a2; t[(k << 2) + 3] = a3;
                m1 = fmaxf(m1, fmaxf(fmaxf(a0, a1), fmaxf(a2, a3)));
            }
#pragma unroll
            for (int o = 16; o; o >>= 1) m1 = fmaxf(m1, __shfl_xor_sync(0xffffffffu, m1, o));
            float s1 = 0.f;
#pragma unroll
            for (int q = 0; q < 16; ++q) s1 += ex2(t[q] - m1);

            float m2 = -3.0e38f;
#pragma unroll
            for (int k = 4; k < 8; ++k) {
                int i4 = (k << 5) + lane;
                float4 c = __ldcg(&ct4[i4]);
                float4 v = *(const float4*)(shv + (i4 << 2));
                float a0 = fmaf(c.x, -KAP, v.x), a1 = fmaf(c.y, -KAP, v.y);
                float a2 = fmaf(c.z, -KAP, v.z), a3 = fmaf(c.w, -KAP, v.w);
                t[((k - 4) << 2) + 0] = a0; t[((k - 4) << 2) + 1] = a1;
                t[((k - 4) << 2) + 2] = a2; t[((k - 4) << 2) + 3] = a3;
                m2 = fmaxf(m2, fmaxf(fmaxf(a0, a1), fmaxf(a2, a3)));
            }
#pragma unroll
            for (int o = 16; o; o >>= 1) m2 = fmaxf(m2, __shfl_xor_sync(0xffffffffu, m2, o));
            float s2 = 0.f;
#pragma unroll
            for (int q = 0; q < 16; ++q) s2 += ex2(t[q] - m2);

            float M = fmaxf(m1, m2);
            float S = s1 * ex2(m1 - M) + s2 * ex2(m2 - M);
#pragma unroll
            for (int o = 16; o; o >>= 1) S += __shfl_xor_sync(0xffffffffu, S, o);
            float v_raw = EPSF * lnu - EPSLN2 * (M + lg2(S));
            if (lane == 0) __stcg(&g_v[(n << 10) + jc], v_raw * KAP);
        }
        gbar(n, bb, ep++);                       // group: all g_v visible
    }

    // ---------------- epilogue: pi rows + per-row cost partial ----------------
    __syncthreads();
    shv[tid] = __ldcg(&g_v[(n << 10) + tid]);    // kappa*v (fresh)
    __syncthreads();
    {
        const float* trow = tile + (w << 10);
        float* prow = pi + ((size_t)r << 10);
        float uk = up * KAP;
        float acc = 0.f;
#pragma unroll
        for (int k = 0; k < 8; ++k) {
            int idx = (lane << 2) + (k << 7);
            float4 c = *(const float4*)(trow + idx);
            float4 v = *(const float4*)(shv + idx);
            float4 p;
            p.x = ex2(uk + v.x - c.x);
            p.y = ex2(uk + v.y - c.y);
            p.z = ex2(uk + v.z - c.z);
            p.w = ex2(uk + v.w - c.w);
            __stcg((float4*)(prow + idx), p);
            acc += p.x * c.x + p.y * c.y + p.z * c.z + p.w * c.w;
        }
#pragma unroll
        for (int o = 16; o; o >>= 1) acc += __shfl_xor_sync(0xffffffffu, acc, o);
        if (lane == 0) __stcg(&g_rowPart[r], acc * EPSLN2);   // undo kappa on C
    }
}

// ----------------------------- kernel 4: deterministic cost reduce ----------
__global__ void k_final(float* __restrict__ cost) {
    int tid = threadIdx.x;   // 128
    int n = tid >> 5, lane = tid & 31;
    float s = 0.f;
#pragma unroll
    for (int q = 0; q < 32; ++q) s += g_rowPart[(n << 10) + lane + (q << 5)];
#pragma unroll
    for (int o = 16; o; o >>= 1) s += __shfl_xor_sync(0xffffffffu, s, o);
    if (lane == 0) cost[n] = s;
}

// ----------------------------- launch ---------------------------------------
#define SINK_SMEM ((32*1024 + 1024 + 32) * 4 + 64)

extern "C" void kernel_launch(void* const* d_in, const int* in_sizes, int n_in,
                              void* d_out, int out_size) {
    const float* x  = (const float*)d_in[0];
    const float* y  = (const float*)d_in[1];
    const float* wx = (const float*)d_in[2];
    const float* wy = (const float*)d_in[3];

    float* out  = (float*)d_out;
    float* cost = out;                 // [4]
    float* pi   = out + NB;            // [4,1024,1024]
    float* C    = out + NB + PLANE;    // [4,1024,1024]

    cudaFuncSetAttribute(k_sink, cudaFuncAttributeMaxDynamicSharedMemorySize, SINK_SMEM);

    k_init<<<4, 1024>>>(wx, wy);
    dim3 gc(32, 32, 4);
    k_cost<<<gc, 256>>>(x, y, C);
    k_flags<<<1, 128>>>();
    k_sink<<<SBLOCKS, STHREADS, SINK_SMEM>>>(C, pi);
    k_final<<<1, 128>>>(cost);
}